// round 1
// baseline (speedup 1.0000x reference)
#include <cuda_runtime.h>

// out[b,t,s] = dot(q[b,t,:], E_h[s - t/4 + 255])
//   E_h[j] = e1[h*256 + j]        for j in [0,256)
//   E_h[j] = e2[h*256 + j - 255]  for j in [256,511)
//   h = b % 8
//
// B=128, T=1024, S=256, D=64.

#define T_DIM 1024
#define S_DIM 256
#define D_DIM 64

constexpr int BT  = 32;              // t-rows per block (8 sh-groups)
constexpr int BSC = 128;             // s-cols per block
constexpr int WIN = BSC + BT / 4 - 1;   // 135 E-rows staged
constexpr int KP  = 68;              // padded k stride (conflict-free LDS.128)

__global__ __launch_bounds__(128)
void srel_attn_kernel(const float* __restrict__ q,
                      const float* __restrict__ e1,
                      const float* __restrict__ e2,
                      float* __restrict__ out)
{
    __shared__ float As[BT * KP];    //  8.7 KB
    __shared__ float Bs[WIN * KP];   // 36.7 KB

    const int tid = threadIdx.x;
    const int tx  = tid & 15;        // 0..15  (s)
    const int ty  = tid >> 4;        // 0..7   (sh-group within tile)
    const int t0  = blockIdx.x * BT;
    const int sx  = blockIdx.y;      // 0..1
    const int b   = blockIdx.z;      // 0..127
    const int h   = b & 7;
    const int sh0 = t0 >> 2;
    // window covers j in [jmin, jmin+WIN) where j = s - sh + 255
    const int jmin = BSC * sx + 255 - (sh0 + BT / 4 - 1);   // = BSC*sx + 248 - sh0

    // ---- stage q tile: As[t][k] (row-major, k padded) ----
    const float* qbase = q + ((size_t)b * T_DIM + t0) * D_DIM;
    for (int idx = tid; idx < BT * 16; idx += 128) {
        int row = idx >> 4, m = idx & 15;
        float4 v = *reinterpret_cast<const float4*>(qbase + row * D_DIM + 4 * m);
        *reinterpret_cast<float4*>(&As[row * KP + 4 * m]) = v;
    }
    // ---- stage E window: Bs[r][k], r = j - jmin ----
    for (int idx = tid; idx < WIN * 16; idx += 128) {
        int r = idx >> 4, m = idx & 15;
        int j = jmin + r;
        const float* src = (j < 256)
            ? (e1 + (size_t)(h * 256 + j) * D_DIM)
            : (e2 + (size_t)(h * 256 + j - 255) * D_DIM);
        float4 v = *reinterpret_cast<const float4*>(src + 4 * m);
        *reinterpret_cast<float4*>(&Bs[r * KP + 4 * m]) = v;
    }
    __syncthreads();

    float acc[4][8];
    #pragma unroll
    for (int i = 0; i < 4; i++)
        #pragma unroll
        for (int jj = 0; jj < 8; jj++)
            acc[i][jj] = 0.0f;

    // all 4 t-rows of this thread share sh = sh0 + ty, so one column offset:
    // local col = (s_local) + (BT/4 - 1) - ty
    const int off = (BT / 4 - 1) - ty;   // 7 - ty

    #pragma unroll
    for (int k4 = 0; k4 < D_DIM / 4; k4++) {
        float4 a[4];
        float4 bv[8];
        #pragma unroll
        for (int i = 0; i < 4; i++)
            a[i] = *reinterpret_cast<const float4*>(&As[(ty * 4 + i) * KP + 4 * k4]);
        #pragma unroll
        for (int jj = 0; jj < 8; jj++)
            bv[jj] = *reinterpret_cast<const float4*>(&Bs[(off + tx + 16 * jj) * KP + 4 * k4]);
        #pragma unroll
        for (int i = 0; i < 4; i++) {
            #pragma unroll
            for (int jj = 0; jj < 8; jj++) {
                acc[i][jj] = fmaf(a[i].x, bv[jj].x, acc[i][jj]);
                acc[i][jj] = fmaf(a[i].y, bv[jj].y, acc[i][jj]);
                acc[i][jj] = fmaf(a[i].z, bv[jj].z, acc[i][jj]);
                acc[i][jj] = fmaf(a[i].w, bv[jj].w, acc[i][jj]);
            }
        }
    }

    float* obase = out + ((size_t)b * T_DIM + t0) * S_DIM + BSC * sx;
    #pragma unroll
    for (int i = 0; i < 4; i++)
        #pragma unroll
        for (int jj = 0; jj < 8; jj++)
            obase[(ty * 4 + i) * S_DIM + tx + 16 * jj] = acc[i][jj];
}

extern "C" void kernel_launch(void* const* d_in, const int* in_sizes, int n_in,
                              void* d_out, int out_size)
{
    const float* q  = (const float*)d_in[0];
    const float* e1 = (const float*)d_in[1];
    const float* e2 = (const float*)d_in[2];
    float* out = (float*)d_out;

    dim3 grid(T_DIM / BT, S_DIM / BSC, 128);   // (32, 2, 128)
    srel_attn_kernel<<<grid, 128>>>(q, e1, e2, out);
}

// round 3
// speedup vs baseline: 1.1662x; 1.1662x over previous
#include <cuda_runtime.h>
#include <cuda_bf16.h>
#include <cstdint>

// out[b,t,s] = dot(q[b,t,:], E_h[s - t/4 + 255]),  h = b % 8
//   E_h[j] = e1[h*256 + j]        j in [0,256)
//   E_h[j] = e2[h*256 + j - 255]  j in [256,511)
// B=128, T=1024, S=256, D=64.
//
// Per block: one b, 128 t-rows, 128 s-cols (half of S).
// Banded GEMM M=128 (t) x N=160 (E window) x K=64, 3-way bf16 split:
//   D = qh*Eh + qh*El + ql*Eh     (ql*El dropped, ~2^-16)
// out[t_loc][s_loc] = D[t_loc][ s_loc + 31 - t_loc/4 ]
//
// mma.sync.m16n8k16 bf16 (HMMA path — tcgen05 unavailable on compute_103 PTX target).

#define T_DIM 1024
#define S_DIM 256
#define D_DIM 64

constexpr int BT = 128;          // t-rows per block
constexpr int NW = 160;          // E-window rows staged (cols 0..158 consumed)
constexpr int RSTRIDE = 144;     // bytes per bf16 row (72 bf16): conflict-free LDSM
constexpr int SP = 168;          // fp32 staging stride (floats)

constexpr int SM_AH = 0;
constexpr int SM_AL = SM_AH + BT * RSTRIDE;      // 18432
constexpr int SM_BH = SM_AL + BT * RSTRIDE;      // 36864
constexpr int SM_BL = SM_BH + NW * RSTRIDE;      // 59904
constexpr int SM_IN_END = SM_BL + NW * RSTRIDE;  // 82944
constexpr int SM_STAGE = 0;                      // fp32 stage aliases inputs
constexpr int SM_TOTAL = BT * SP * 4;            // 86016
static_assert(SM_TOTAL >= SM_IN_END, "stage must cover inputs");

__device__ __forceinline__ uint32_t smem_u32(const void* p) {
    uint32_t a;
    asm("{ .reg .u64 t; cvta.to.shared.u64 t, %1; cvt.u32.u64 %0, t; }"
        : "=r"(a) : "l"(p));
    return a;
}

#define LDSM_X4(r0, r1, r2, r3, addr)                                        \
    asm volatile("ldmatrix.sync.aligned.m8n8.x4.shared.b16 {%0,%1,%2,%3}, [%4];" \
                 : "=r"(r0), "=r"(r1), "=r"(r2), "=r"(r3) : "r"(addr))

#define LDSM_X2(r0, r1, addr)                                                \
    asm volatile("ldmatrix.sync.aligned.m8n8.x2.shared.b16 {%0,%1}, [%2];"   \
                 : "=r"(r0), "=r"(r1) : "r"(addr))

#define MMA16816(d, a, bb)                                                   \
    asm volatile("mma.sync.aligned.m16n8k16.row.col.f32.bf16.bf16.f32 "      \
                 "{%0,%1,%2,%3}, {%4,%5,%6,%7}, {%8,%9}, {%0,%1,%2,%3};"     \
                 : "+f"((d)[0]), "+f"((d)[1]), "+f"((d)[2]), "+f"((d)[3])    \
                 : "r"((a)[0]), "r"((a)[1]), "r"((a)[2]), "r"((a)[3]),       \
                   "r"((bb)[0]), "r"((bb)[1]))

__device__ __forceinline__ void split2(float a, float b, uint32_t& hi, uint32_t& lo) {
    __nv_bfloat16 ha = __float2bfloat16(a);
    __nv_bfloat16 hb = __float2bfloat16(b);
    __nv_bfloat16 la = __float2bfloat16(a - __bfloat162float(ha));
    __nv_bfloat16 lb = __float2bfloat16(b - __bfloat162float(hb));
    __nv_bfloat162 H; H.x = ha; H.y = hb;
    __nv_bfloat162 L; L.x = la; L.y = lb;
    hi = *reinterpret_cast<uint32_t*>(&H);
    lo = *reinterpret_cast<uint32_t*>(&L);
}

__global__ void __launch_bounds__(256, 2)
srel_mma(const float* __restrict__ q,
         const float* __restrict__ e1,
         const float* __restrict__ e2,
         float* __restrict__ out)
{
    extern __shared__ char smem[];
    const uint32_t sb = smem_u32(smem);
    const int tid  = threadIdx.x;
    const int lane = tid & 31;
    const int wid  = tid >> 5;

    const int b   = blockIdx.z;
    const int h   = b & 7;
    const int t0  = blockIdx.x * BT;
    const int sx  = blockIdx.y;
    const int sh0 = t0 >> 2;
    const int jmin = 128 * sx + 224 - sh0;   // window j = jmin + c, c in [0,159]

    // ---- stage Q: bf16 hi/lo tiles, 144B rows ----
    const float* qb = q + ((size_t)b * T_DIM + t0) * D_DIM;
    for (int idx = tid; idx < BT * 16; idx += 256) {
        int row = idx >> 4, m = idx & 15;
        float4 v = *reinterpret_cast<const float4*>(qb + row * D_DIM + 4 * m);
        uint32_t h0, l0, h1, l1;
        split2(v.x, v.y, h0, l0);
        split2(v.z, v.w, h1, l1);
        uint32_t* pH = reinterpret_cast<uint32_t*>(smem + SM_AH + row * RSTRIDE + 8 * m);
        uint32_t* pL = reinterpret_cast<uint32_t*>(smem + SM_AL + row * RSTRIDE + 8 * m);
        pH[0] = h0; pH[1] = h1;
        pL[0] = l0; pL[1] = l1;
    }
    // ---- stage E window: bf16 hi/lo tiles ----
    for (int idx = tid; idx < NW * 16; idx += 256) {
        int r = idx >> 4, m = idx & 15;
        int j = jmin + r;
        if (j > 510) j = 510;   // col 159 never consumed; keep read in-bounds
        const float* src = (j < 256)
            ? (e1 + (size_t)(h * 256 + j) * D_DIM)
            : (e2 + (size_t)(h * 256 + j - 255) * D_DIM);
        float4 v = *reinterpret_cast<const float4*>(src + 4 * m);
        uint32_t h0, l0, h1, l1;
        split2(v.x, v.y, h0, l0);
        split2(v.z, v.w, h1, l1);
        uint32_t* pH = reinterpret_cast<uint32_t*>(smem + SM_BH + r * RSTRIDE + 8 * m);
        uint32_t* pL = reinterpret_cast<uint32_t*>(smem + SM_BL + r * RSTRIDE + 8 * m);
        pH[0] = h0; pH[1] = h1;
        pL[0] = l0; pL[1] = l1;
    }
    __syncthreads();

    // ---- warp tiling: 8 warps = 2 (M halves of 64) x 4 (N quarters of 40) ----
    const int wm = wid & 1;
    const int wn = wid >> 1;
    const int g  = lane >> 2;
    const int tg = lane & 3;

    float acc[4][5][4] = {};   // [m-tile 16][n-tile 8][frag]

    // ldmatrix per-lane byte offsets within a tile
    const uint32_t aOff = (uint32_t)(wm * 64 + (lane & 15)) * RSTRIDE + (lane >> 4) * 16;
    const uint32_t bOff = (uint32_t)(wn * 40 + (lane & 7)) * RSTRIDE + ((lane >> 3) & 1) * 16;

    #pragma unroll
    for (int pass = 0; pass < 3; pass++) {
        const uint32_t aBase = sb + (pass < 2 ? SM_AH : SM_AL) + aOff;
        const uint32_t bBase = sb + (pass == 1 ? SM_BL : SM_BH) + bOff;
        #pragma unroll
        for (int kk = 0; kk < 4; kk++) {          // K=64 in 4 steps of 16
            uint32_t a[4][4], bf[5][2];
            #pragma unroll
            for (int mt = 0; mt < 4; mt++)
                LDSM_X4(a[mt][0], a[mt][1], a[mt][2], a[mt][3],
                        aBase + mt * 16 * RSTRIDE + kk * 32);
            #pragma unroll
            for (int nt = 0; nt < 5; nt++)
                LDSM_X2(bf[nt][0], bf[nt][1],
                        bBase + nt * 8 * RSTRIDE + kk * 32);
            #pragma unroll
            for (int mt = 0; mt < 4; mt++)
                #pragma unroll
                for (int nt = 0; nt < 5; nt++)
                    MMA16816(acc[mt][nt], a[mt], bf[nt]);
        }
    }
    __syncthreads();   // all warps done reading input tiles; stage may alias them

    // ---- accum -> fp32 staging (window coords) ----
    float* st = reinterpret_cast<float*>(smem + SM_STAGE);
    #pragma unroll
    for (int mt = 0; mt < 4; mt++) {
        const int m0 = wm * 64 + mt * 16 + g;
        #pragma unroll
        for (int nt = 0; nt < 5; nt++) {
            const int n = wn * 40 + nt * 8 + 2 * tg;
            *reinterpret_cast<float2*>(&st[m0 * SP + n]) =
                make_float2(acc[mt][nt][0], acc[mt][nt][1]);
            *reinterpret_cast<float2*>(&st[(m0 + 8) * SP + n]) =
                make_float2(acc[mt][nt][2], acc[mt][nt][3]);
        }
    }
    __syncthreads();

    // ---- shifted read + coalesced float4 writeout ----
    float* ob = out + ((size_t)b * T_DIM + t0) * S_DIM + 128 * sx;
    for (int idx = tid; idx < 128 * 32; idx += 256) {
        int row = idx >> 5, m = idx & 31;
        int off = 31 - (row >> 2);
        const float* sr = &st[row * SP + 4 * m + off];
        float4 v = make_float4(sr[0], sr[1], sr[2], sr[3]);
        *reinterpret_cast<float4*>(ob + row * S_DIM + 4 * m) = v;
    }
}

extern "C" void kernel_launch(void* const* d_in, const int* in_sizes, int n_in,
                              void* d_out, int out_size)
{
    const float* q  = (const float*)d_in[0];
    const float* e1 = (const float*)d_in[1];
    const float* e2 = (const float*)d_in[2];
    float* out = (float*)d_out;

    cudaFuncSetAttribute(srel_mma,
                         cudaFuncAttributeMaxDynamicSharedMemorySize, SM_TOTAL);
    dim3 grid(T_DIM / BT, S_DIM / 128, 128);   // (8, 2, 128) = 2048 blocks
    srel_mma<<<grid, 256, SM_TOTAL>>>(q, e1, e2, out);
}

// round 5
// speedup vs baseline: 2.2132x; 1.8978x over previous
#include <cuda_runtime.h>
#include <cuda_bf16.h>
#include <cstdint>

// out[b,t,s] = dot(q[b,t,:], E_h[s - t/4 + 255]),  h = b % 8
//   E_h[j] = e1[h*256 + j]        j in [0,256)
//   E_h[j] = e2[h*256 + j - 255]  j in [256,511)
// B=128, T=1024, S=256, D=64.
//
// Per block: one b, 128 t-rows, 128 s-cols.
// Banded GEMM M=128 x N=160 (window) x K=64, truncation bf16 split:
//   x = xh + xl, xh = trunc16(x) (xl exactly bf16)
//   D = qh*Eh + qh*El + ql*Eh     (ql*El dropped, ~2^-16)
// out[t][s] = D[t][ s + 31 - t/4 ]

#define T_DIM 1024
#define S_DIM 256
#define D_DIM 64

constexpr int BT = 128;
constexpr int NW = 160;
constexpr int RSTRIDE = 144;     // bytes per bf16 row: conflict-free LDSM
constexpr int SP = 168;          // fp32 staging stride (floats)

constexpr int SM_AH = 0;
constexpr int SM_AL = SM_AH + BT * RSTRIDE;      // 18432
constexpr int SM_BH = SM_AL + BT * RSTRIDE;      // 36864
constexpr int SM_BL = SM_BH + NW * RSTRIDE;      // 59904
constexpr int SM_IN_END = SM_BL + NW * RSTRIDE;  // 82944
constexpr int SM_TOTAL = BT * SP * 4;            // 86016 (stage aliases inputs)
static_assert(SM_TOTAL >= SM_IN_END, "stage must cover inputs");

__device__ __forceinline__ uint32_t smem_u32(const void* p) {
    uint32_t a;
    asm("{ .reg .u64 t; cvta.to.shared.u64 t, %1; cvt.u32.u64 %0, t; }"
        : "=r"(a) : "l"(p));
    return a;
}

#define LDSM_X4(r0, r1, r2, r3, addr)                                        \
    asm volatile("ldmatrix.sync.aligned.m8n8.x4.shared.b16 {%0,%1,%2,%3}, [%4];" \
                 : "=r"(r0), "=r"(r1), "=r"(r2), "=r"(r3) : "r"(addr))

#define LDSM_X2(r0, r1, addr)                                                \
    asm volatile("ldmatrix.sync.aligned.m8n8.x2.shared.b16 {%0,%1}, [%2];"   \
                 : "=r"(r0), "=r"(r1) : "r"(addr))

#define MMA16816(d, a, bb)                                                   \
    asm volatile("mma.sync.aligned.m16n8k16.row.col.f32.bf16.bf16.f32 "      \
                 "{%0,%1,%2,%3}, {%4,%5,%6,%7}, {%8,%9}, {%0,%1,%2,%3};"     \
                 : "+f"((d)[0]), "+f"((d)[1]), "+f"((d)[2]), "+f"((d)[3])    \
                 : "r"((a)[0]), "r"((a)[1]), "r"((a)[2]), "r"((a)[3]),       \
                   "r"((bb)[0]), "r"((bb)[1]))

// truncation split of two floats: hi = top16 bits (packed), lo = exact remainder
__device__ __forceinline__ void split2t(float a, float b, uint32_t& hi, uint32_t& lo) {
    uint32_t ua = __float_as_uint(a), ub = __float_as_uint(b);
    hi = __byte_perm(ua, ub, 0x7632);
    float ra = a - __uint_as_float(ua & 0xFFFF0000u);
    float rb = b - __uint_as_float(ub & 0xFFFF0000u);
    __nv_bfloat162 L = __floats2bfloat162_rn(ra, rb);   // exact
    lo = *reinterpret_cast<uint32_t*>(&L);
}

__global__ void __launch_bounds__(256, 2)
srel_mma(const float* __restrict__ q,
         const float* __restrict__ e1,
         const float* __restrict__ e2,
         float* __restrict__ out)
{
    extern __shared__ char smem[];
    const uint32_t sb = smem_u32(smem);
    const int tid  = threadIdx.x;
    const int lane = tid & 31;
    const int wid  = tid >> 5;

    const int b   = blockIdx.z;
    const int h   = b & 7;
    const int t0  = blockIdx.x * BT;
    const int sx  = blockIdx.y;
    const int sh0 = t0 >> 2;
    const int jmin = 128 * sx + 224 - sh0;   // window j = jmin + c, c in [0,159]

    // ---- stage Q: batch loads for MLP, then split+STS ----
    {
        const float* qb = q + ((size_t)b * T_DIM + t0) * D_DIM;
        float4 v[8];
        #pragma unroll
        for (int i = 0; i < 8; i++) {
            int idx = tid + 256 * i;
            int row = idx >> 4, m = idx & 15;
            v[i] = *reinterpret_cast<const float4*>(qb + row * D_DIM + 4 * m);
        }
        #pragma unroll
        for (int i = 0; i < 8; i++) {
            int idx = tid + 256 * i;
            int row = idx >> 4, m = idx & 15;
            uint32_t h0, l0, h1, l1;
            split2t(v[i].x, v[i].y, h0, l0);
            split2t(v[i].z, v[i].w, h1, l1);
            uint32_t* pH = reinterpret_cast<uint32_t*>(smem + SM_AH + row * RSTRIDE + 8 * m);
            uint32_t* pL = reinterpret_cast<uint32_t*>(smem + SM_AL + row * RSTRIDE + 8 * m);
            pH[0] = h0; pH[1] = h1;
            pL[0] = l0; pL[1] = l1;
        }
    }
    // ---- stage E window ----
    {
        float4 v[10];
        #pragma unroll
        for (int i = 0; i < 10; i++) {
            int idx = tid + 256 * i;
            int r = idx >> 4, m = idx & 15;
            int j = jmin + r;
            if (j > 510) j = 510;   // col 159 never consumed
            const float* src = (j < 256)
                ? (e1 + (size_t)(h * 256 + j) * D_DIM)
                : (e2 + (size_t)(h * 256 + j - 255) * D_DIM);
            v[i] = *reinterpret_cast<const float4*>(src + 4 * m);
        }
        #pragma unroll
        for (int i = 0; i < 10; i++) {
            int idx = tid + 256 * i;
            int r = idx >> 4, m = idx & 15;
            uint32_t h0, l0, h1, l1;
            split2t(v[i].x, v[i].y, h0, l0);
            split2t(v[i].z, v[i].w, h1, l1);
            uint32_t* pH = reinterpret_cast<uint32_t*>(smem + SM_BH + r * RSTRIDE + 8 * m);
            uint32_t* pL = reinterpret_cast<uint32_t*>(smem + SM_BL + r * RSTRIDE + 8 * m);
            pH[0] = h0; pH[1] = h1;
            pL[0] = l0; pL[1] = l1;
        }
    }
    __syncthreads();

    // ---- warp tiling: 8 warps = 2 (M halves 64) x 4 (N quarters 40) ----
    const int wm = wid & 1;
    const int wn = wid >> 1;
    const int g  = lane >> 2;
    const int tg = lane & 3;

    float acc[4][5][4] = {};

    const uint32_t aOff = (uint32_t)(wm * 64 + (lane & 15)) * RSTRIDE + (lane >> 4) * 16;
    const uint32_t bOff = (uint32_t)(wn * 40 + (lane & 7)) * RSTRIDE + ((lane >> 3) & 1) * 16;
    const uint32_t aH0 = sb + SM_AH + aOff;
    const uint32_t aL0 = sb + SM_AL + aOff;
    const uint32_t bH0 = sb + SM_BH + bOff;
    const uint32_t bL0 = sb + SM_BL + bOff;

    #pragma unroll
    for (int kk = 0; kk < 4; kk++) {
        uint32_t aH[4][4], aL[4][4], bH[5][2], bL[5][2];
        // pass 1: qh * Eh
        #pragma unroll
        for (int mt = 0; mt < 4; mt++)
            LDSM_X4(aH[mt][0], aH[mt][1], aH[mt][2], aH[mt][3],
                    aH0 + mt * 16 * RSTRIDE + kk * 32);
        #pragma unroll
        for (int nt = 0; nt < 5; nt++)
            LDSM_X2(bH[nt][0], bH[nt][1], bH0 + nt * 8 * RSTRIDE + kk * 32);
        #pragma unroll
        for (int mt = 0; mt < 4; mt++)
            #pragma unroll
            for (int nt = 0; nt < 5; nt++)
                MMA16816(acc[mt][nt], aH[mt], bH[nt]);
        // pass 2: qh * El   (reuse aH)
        #pragma unroll
        for (int nt = 0; nt < 5; nt++)
            LDSM_X2(bL[nt][0], bL[nt][1], bL0 + nt * 8 * RSTRIDE + kk * 32);
        #pragma unroll
        for (int mt = 0; mt < 4; mt++)
            #pragma unroll
            for (int nt = 0; nt < 5; nt++)
                MMA16816(acc[mt][nt], aH[mt], bL[nt]);
        // pass 3: ql * Eh   (reuse bH)
        #pragma unroll
        for (int mt = 0; mt < 4; mt++)
            LDSM_X4(aL[mt][0], aL[mt][1], aL[mt][2], aL[mt][3],
                    aL0 + mt * 16 * RSTRIDE + kk * 32);
        #pragma unroll
        for (int mt = 0; mt < 4; mt++)
            #pragma unroll
            for (int nt = 0; nt < 5; nt++)
                MMA16816(acc[mt][nt], aL[mt], bH[nt]);
    }
    __syncthreads();   // inputs dead; stage may alias

    // ---- accum -> fp32 staging (window coords) ----
    float* st = reinterpret_cast<float*>(smem);
    #pragma unroll
    for (int mt = 0; mt < 4; mt++) {
        const int m0 = wm * 64 + mt * 16 + g;
        #pragma unroll
        for (int nt = 0; nt < 5; nt++) {
            const int n = wn * 40 + nt * 8 + 2 * tg;
            *reinterpret_cast<float2*>(&st[m0 * SP + n]) =
                make_float2(acc[mt][nt][0], acc[mt][nt][1]);
            *reinterpret_cast<float2*>(&st[(m0 + 8) * SP + n]) =
                make_float2(acc[mt][nt][2], acc[mt][nt][3]);
        }
    }
    __syncthreads();

    // ---- shifted read (conflict-free column-strided) + coalesced writeout ----
    float* ob = out + ((size_t)b * T_DIM + t0) * S_DIM + 128 * sx;
    #pragma unroll
    for (int it = 0; it < 16; it++) {
        int idx = tid + 256 * it;
        int row = idx >> 5, m = idx & 31;
        int off = 31 - (row >> 2);
        const float* sr = &st[row * SP + off];
        float* orow = ob + row * S_DIM;
        #pragma unroll
        for (int k = 0; k < 4; k++)
            orow[m + 32 * k] = sr[m + 32 * k];
    }
}

extern "C" void kernel_launch(void* const* d_in, const int* in_sizes, int n_in,
                              void* d_out, int out_size)
{
    const float* q  = (const float*)d_in[0];
    const float* e1 = (const float*)d_in[1];
    const float* e2 = (const float*)d_in[2];
    float* out = (float*)d_out;

    cudaFuncSetAttribute(srel_mma,
                         cudaFuncAttributeMaxDynamicSharedMemorySize, SM_TOTAL);
    dim3 grid(T_DIM / BT, S_DIM / 128, 128);   // 2048 blocks
    srel_mma<<<grid, 256, SM_TOTAL>>>(q, e1, e2, out);
}